// round 1
// baseline (speedup 1.0000x reference)
#include <cuda_runtime.h>
#include <float.h>

#define Bg   64
#define Lg   1024
#define Kn   16
#define INF_ 128
#define OUTF 128
#define Sd   4
#define FLRd 64
#define Ntot (Bg * Lg)

// ---- scratch (static device globals; no allocation allowed) ----
__device__ float g_s[Ntot * Sd];          //  1 MB   learned kNN space
__device__ float g_h[Ntot * FLRd];        // 16 MB   propagated features
__device__ float g_w[Ntot * Kn];          //  4 MB   edge weights
__device__ int   g_id[Ntot * Kn];         //  4 MB   neighbor indices (global)
__device__ float g_agg[Ntot * 2 * FLRd];  // 32 MB   [mean(64) | max(64)] per node

// ============================================================
// Kernel 1: fused s/h embedding.  warp-per-row, W in smem.
//   combined W columns: 0..63 = W_h, 64..67 = W_s
// ============================================================
__global__ __launch_bounds__(256) void k_embed(
    const float* __restrict__ x,
    const float* __restrict__ Ws, const float* __restrict__ bs,
    const float* __restrict__ Wh, const float* __restrict__ bh)
{
    __shared__ float Wc[128 * 68];
    __shared__ float xs[8][128];

    int t = threadIdx.x;
    for (int i = t; i < 128 * 68; i += 256) {
        int k = i / 68, c = i % 68;
        Wc[i] = (c < 64) ? Wh[k * 64 + c] : Ws[k * 4 + (c - 64)];
    }

    int warp = t >> 5, lane = t & 31;
    int row = blockIdx.x * 8 + warp;

    const float4* xr = (const float4*)(x + row * 128);
    ((float4*)&xs[warp][0])[lane] = xr[lane];   // 32 lanes * float4 = 128 floats
    __syncthreads();

    float a0 = 0.f, a1 = 0.f, a2 = 0.f;
#pragma unroll 8
    for (int k = 0; k < 128; k++) {
        float xv = xs[warp][k];
        a0 = fmaf(xv, Wc[k * 68 + lane], a0);
        a1 = fmaf(xv, Wc[k * 68 + 32 + lane], a1);
        if (lane < 4) a2 = fmaf(xv, Wc[k * 68 + 64 + lane], a2);
    }
    g_h[row * 64 + lane]      = a0 + bh[lane];
    g_h[row * 64 + 32 + lane] = a1 + bh[32 + lane];
    if (lane < 4) g_s[row * 4 + lane] = a2 + bs[lane];
}

// ============================================================
// Kernel 2: per-graph kNN (K=16 smallest d2, self included) +
//           edge weights w = exp(-10*d2).
//   grid (64 graphs, 2 halves) x 512 threads; s tile in smem.
// ============================================================
__global__ __launch_bounds__(512) void k_knn()
{
    __shared__ float4 sg[Lg];
    int b = blockIdx.x;
    int base = b * Lg;

    const float4* sp = (const float4*)(g_s + base * 4);
    for (int i = threadIdx.x; i < Lg; i += blockDim.x) sg[i] = sp[i];
    __syncthreads();

    int i = blockIdx.y * blockDim.x + threadIdx.x;   // row within graph
    float4 si = sg[i];

    float dist[Kn];
    int   idxv[Kn];
#pragma unroll
    for (int t = 0; t < Kn; t++) { dist[t] = FLT_MAX; idxv[t] = 0; }

    for (int j = 0; j < Lg; j++) {
        float4 sj = sg[j];
        float dx = si.x - sj.x, dy = si.y - sj.y;
        float dz = si.z - sj.z, dw = si.w - sj.w;
        float d2 = dx * dx + dy * dy;
        d2 = fmaf(dz, dz, d2);
        d2 = fmaf(dw, dw, d2);
        if (d2 < dist[Kn - 1]) {
            float dd = d2; int ii = j;
#pragma unroll
            for (int t = 0; t < Kn; t++) {       // sorted insertion, all-static indices
                if (dd < dist[t]) {
                    float td = dist[t]; int ti = idxv[t];
                    dist[t] = dd;  idxv[t] = ii;
                    dd = td;       ii = ti;
                }
            }
        }
    }

#pragma unroll
    for (int t = 0; t < Kn; t++) {
        g_id[(base + i) * Kn + t] = base + idxv[t];
        g_w [(base + i) * Kn + t] = __expf(-10.f * dist[t]);
    }
}

// ============================================================
// Kernel 3: warp-per-node neighbor gather + mean/max aggregation.
//   agg layout per node: [0..63] mean, [64..127] max
// ============================================================
__global__ __launch_bounds__(256) void k_agg()
{
    int node = (blockIdx.x * blockDim.x + threadIdx.x) >> 5;
    int lane = threadIdx.x & 31;
    if (node >= Ntot) return;

    const int*   idp = g_id + node * Kn;
    const float* wp  = g_w  + node * Kn;

    float s0 = 0.f, s1 = 0.f, m0 = -FLT_MAX, m1 = -FLT_MAX;
#pragma unroll
    for (int nb = 0; nb < Kn; nb++) {
        int   id = idp[nb];
        float wt = wp[nb];
        float v0 = g_h[id * 64 + lane]      * wt;
        float v1 = g_h[id * 64 + 32 + lane] * wt;
        s0 += v0;  s1 += v1;
        m0 = fmaxf(m0, v0);  m1 = fmaxf(m1, v1);
    }
    float* ap = g_agg + node * 128;
    ap[lane]      = s0 * (1.f / 16.f);
    ap[32 + lane] = s1 * (1.f / 16.f);
    ap[64 + lane] = m0;
    ap[96 + lane] = m1;
}

// ============================================================
// Kernel 4: out = relu([x | agg] @ W_out + b_out)
//   A logical [N, 256]: k<128 from x, k>=128 from g_agg (both stride 128).
//   128x128x32 smem tiles, 256 threads, 8x8 register tile.
// ============================================================
#define BM 128
#define BN 128
#define BK 32

__global__ __launch_bounds__(256) void k_out(
    const float* __restrict__ x,
    const float* __restrict__ Wout,
    const float* __restrict__ bout,
    float* __restrict__ out)
{
    __shared__ float As[BK][BM + 4];
    __shared__ float Bs[BK][BN];

    int t = threadIdx.x;
    int block_row = blockIdx.x * BM;
    int tx = t & 15, ty = t >> 4;     // 16x16 thread grid, 8x8 each

    float acc[8][8];
#pragma unroll
    for (int i = 0; i < 8; i++)
#pragma unroll
        for (int j = 0; j < 8; j++) acc[i][j] = 0.f;

    for (int kt = 0; kt < 256; kt += BK) {
        const float* Abase = (kt < 128) ? (x + kt) : (g_agg + (kt - 128));

        // load A tile: 128 rows x 32 k ; 2 threads/row, 16 floats each
        {
            int r  = t >> 1;
            int kc = (t & 1) * 16;
            const float4* src = (const float4*)(Abase + (size_t)(block_row + r) * 128 + kc);
#pragma unroll
            for (int i = 0; i < 4; i++) {
                float4 v = src[i];
                As[kc + i * 4 + 0][r] = v.x;
                As[kc + i * 4 + 1][r] = v.y;
                As[kc + i * 4 + 2][r] = v.z;
                As[kc + i * 4 + 3][r] = v.w;
            }
        }
        // load B tile: 32 rows x 128 cols (1024 float4 total, 4 per thread)
        {
            const float4* src = (const float4*)(Wout + (size_t)kt * 128);
#pragma unroll
            for (int i = 0; i < 4; i++) {
                int lin  = t + i * 256;       // float4 index
                int row  = lin >> 5;
                int col4 = lin & 31;
                ((float4*)&Bs[row][0])[col4] = src[lin];
            }
        }
        __syncthreads();

#pragma unroll
        for (int kk = 0; kk < BK; kk++) {
            float a[8], bb[8];
#pragma unroll
            for (int i = 0; i < 8; i++) a[i] = As[kk][ty * 8 + i];
#pragma unroll
            for (int j = 0; j < 8; j++) bb[j] = Bs[kk][tx * 8 + j];
#pragma unroll
            for (int i = 0; i < 8; i++)
#pragma unroll
                for (int j = 0; j < 8; j++)
                    acc[i][j] = fmaf(a[i], bb[j], acc[i][j]);
        }
        __syncthreads();
    }

    float bias[8];
#pragma unroll
    for (int j = 0; j < 8; j++) bias[j] = bout[tx * 8 + j];

#pragma unroll
    for (int i = 0; i < 8; i++) {
        int row = block_row + ty * 8 + i;
        float4 o0, o1;
        float v[8];
#pragma unroll
        for (int j = 0; j < 8; j++) v[j] = fmaxf(acc[i][j] + bias[j], 0.f);
        o0 = make_float4(v[0], v[1], v[2], v[3]);
        o1 = make_float4(v[4], v[5], v[6], v[7]);
        float4* dst = (float4*)(out + (size_t)row * 128 + tx * 8);
        dst[0] = o0;
        dst[1] = o1;
    }
}

// ============================================================
extern "C" void kernel_launch(void* const* d_in, const int* in_sizes, int n_in,
                              void* d_out, int out_size)
{
    const float* x    = (const float*)d_in[0];
    const float* Ws   = (const float*)d_in[1];
    const float* bs   = (const float*)d_in[2];
    const float* Wh   = (const float*)d_in[3];
    const float* bh   = (const float*)d_in[4];
    const float* Wout = (const float*)d_in[5];
    const float* bout = (const float*)d_in[6];
    // d_in[7] = batch (int64): graphs are contiguous equal chunks; layout is implicit.
    float* out = (float*)d_out;

    k_embed<<<Ntot / 8, 256>>>(x, Ws, bs, Wh, bh);
    k_knn<<<dim3(Bg, 2), 512>>>();
    k_agg<<<Ntot / 8, 256>>>();
    k_out<<<Ntot / BM, 256>>>(x, Wout, bout, out);
}

// round 3
// speedup vs baseline: 1.6317x; 1.6317x over previous
#include <cuda_runtime.h>
#include <cuda_pipeline.h>
#include <float.h>

#define Bg   64
#define Lg   1024
#define Kn   16
#define INF_ 128
#define OUTF 128
#define Sd   4
#define FLRd 64
#define Ntot (Bg * Lg)

// ---- scratch (static device globals; no allocation allowed) ----
__device__ float g_s[Ntot * Sd];          //  1 MB   learned kNN space
__device__ float g_h[Ntot * FLRd];        // 16 MB   propagated features
__device__ float g_w[Ntot * Kn];          //  4 MB   edge weights
__device__ int   g_id[Ntot * Kn];         //  4 MB   neighbor indices (global)
__device__ float g_agg[Ntot * 2 * FLRd];  // 32 MB   [mean(64) | max(64)] per node

// ============================================================
// Kernel 1: fused s/h embedding.
//   32 rows per block (4 per warp) so the 34.8KB weight tile is
//   amortized 4x better; each Wc load feeds 4 rows of FMAs.
// ============================================================
__global__ __launch_bounds__(256) void k_embed(
    const float* __restrict__ x,
    const float* __restrict__ Ws, const float* __restrict__ bs,
    const float* __restrict__ Wh, const float* __restrict__ bh)
{
    __shared__ float Wc[128 * 68 + 32];   // pad: unconditional 64+lane load safe
    __shared__ float xs[32][128];

    int t = threadIdx.x;
    for (int i = t; i < 128 * 68; i += 256) {
        int k = i / 68, c = i % 68;
        Wc[i] = (c < 64) ? Wh[k * 64 + c] : Ws[k * 4 + (c - 64)];
    }

    int base_row = blockIdx.x * 32;
    // load 32 rows of x: 1024 float4
    for (int i = t; i < 1024; i += 256) {
        int r = i >> 5, q = i & 31;
        ((float4*)&xs[r][0])[q] = ((const float4*)(x + (size_t)(base_row + r) * 128))[q];
    }
    __syncthreads();

    int warp = t >> 5, lane = t & 31;
    int r0 = warp * 4;

    float a0[4] = {0.f, 0.f, 0.f, 0.f};
    float a1[4] = {0.f, 0.f, 0.f, 0.f};
    float a2[4] = {0.f, 0.f, 0.f, 0.f};

#pragma unroll 4
    for (int k = 0; k < 128; k++) {
        float w0 = Wc[k * 68 + lane];
        float w1 = Wc[k * 68 + 32 + lane];
        float w2 = Wc[k * 68 + 64 + lane];   // garbage for lane>=4, never stored
#pragma unroll
        for (int r = 0; r < 4; r++) {
            float xv = xs[r0 + r][k];
            a0[r] = fmaf(xv, w0, a0[r]);
            a1[r] = fmaf(xv, w1, a1[r]);
            a2[r] = fmaf(xv, w2, a2[r]);
        }
    }

    float bh0 = bh[lane], bh1 = bh[32 + lane];
#pragma unroll
    for (int r = 0; r < 4; r++) {
        int row = base_row + r0 + r;
        g_h[(size_t)row * 64 + lane]      = a0[r] + bh0;
        g_h[(size_t)row * 64 + 32 + lane] = a1[r] + bh1;
        if (lane < 4) g_s[(size_t)row * 4 + lane] = a2[r] + bs[lane];
    }
}

// ============================================================
// Kernel 2: per-graph kNN, K=16 smallest d2 (self included).
//   (d2,index) packed in ONE float: low 10 mantissa bits replaced
//   by j. Sorted-insert chain = 2 FMNMX per stage, no predicates.
//   Exact d2 recomputed for the 16 winners for the edge weights.
// ============================================================
__global__ __launch_bounds__(512) void k_knn()
{
    __shared__ float4 sg[Lg];
    int b = blockIdx.x;
    int base = b * Lg;

    const float4* sp = (const float4*)(g_s + (size_t)base * 4);
    for (int i = threadIdx.x; i < Lg; i += blockDim.x) sg[i] = sp[i];
    __syncthreads();

    int i = blockIdx.y * blockDim.x + threadIdx.x;   // row within graph
    float4 si = sg[i];

    float lst[Kn];                                   // packed, ascending
#pragma unroll
    for (int tt = 0; tt < Kn; tt++) lst[tt] = FLT_MAX;

#pragma unroll 4
    for (int j = 0; j < Lg; j++) {
        float4 sj = sg[j];
        float dx = si.x - sj.x, dy = si.y - sj.y;
        float dz = si.z - sj.z, dw = si.w - sj.w;
        float d2 = dx * dx + dy * dy;
        d2 = fmaf(dz, dz, d2);
        d2 = fmaf(dw, dw, d2);
        float pv = __uint_as_float((__float_as_uint(d2) & 0xFFFFFC00u) | (unsigned)j);
        if (pv < lst[Kn - 1]) {
            float v = pv;
#pragma unroll
            for (int tt = 0; tt < Kn; tt++) {
                float lo = fminf(v, lst[tt]);
                v       = fmaxf(v, lst[tt]);
                lst[tt] = lo;
            }
        }
    }

    // recover indices, recompute exact d2 for weights, vector stores
    int   oid[Kn];
    float ow [Kn];
#pragma unroll
    for (int tt = 0; tt < Kn; tt++) {
        int j = (int)(__float_as_uint(lst[tt]) & 1023u);
        float4 sj = sg[j];
        float dx = si.x - sj.x, dy = si.y - sj.y;
        float dz = si.z - sj.z, dw = si.w - sj.w;
        float d2 = dx * dx + dy * dy;
        d2 = fmaf(dz, dz, d2);
        d2 = fmaf(dw, dw, d2);
        oid[tt] = base + j;
        ow [tt] = __expf(-10.f * d2);
    }
    int4*   idp = (int4*)  (g_id + (size_t)(base + i) * Kn);
    float4* wp  = (float4*)(g_w  + (size_t)(base + i) * Kn);
#pragma unroll
    for (int q = 0; q < 4; q++) {
        idp[q] = make_int4(oid[q*4], oid[q*4+1], oid[q*4+2], oid[q*4+3]);
        wp [q] = make_float4(ow[q*4], ow[q*4+1], ow[q*4+2], ow[q*4+3]);
    }
}

// ============================================================
// Kernel 3: warp-per-node gather + mean/max aggregation.
//   id/w loaded once by lanes 0..15, broadcast via shfl.
// ============================================================
__global__ __launch_bounds__(256) void k_agg()
{
    int node = (blockIdx.x * blockDim.x + threadIdx.x) >> 5;
    int lane = threadIdx.x & 31;
    if (node >= Ntot) return;

    int   myid = 0;
    float mywt = 0.f;
    if (lane < Kn) {
        myid = g_id[(size_t)node * Kn + lane];
        mywt = g_w [(size_t)node * Kn + lane];
    }

    float s0 = 0.f, s1 = 0.f, m0 = -FLT_MAX, m1 = -FLT_MAX;
#pragma unroll
    for (int nb = 0; nb < Kn; nb++) {
        int   id = __shfl_sync(0xffffffffu, myid, nb);
        float wt = __shfl_sync(0xffffffffu, mywt, nb);
        float v0 = __ldg(&g_h[(size_t)id * 64 + lane])      * wt;
        float v1 = __ldg(&g_h[(size_t)id * 64 + 32 + lane]) * wt;
        s0 += v0;  s1 += v1;
        m0 = fmaxf(m0, v0);  m1 = fmaxf(m1, v1);
    }
    float* ap = g_agg + (size_t)node * 128;
    ap[lane]      = s0 * (1.f / 16.f);
    ap[32 + lane] = s1 * (1.f / 16.f);
    ap[64 + lane] = m0;
    ap[96 + lane] = m1;
}

// ============================================================
// Kernel 4: out = relu([x | agg] @ W_out + b_out)
//   cp.async double-buffered 128x128x16 pipeline; A row-major
//   (pitch 20) so async copies need no transpose.
// ============================================================
#define BM 128
#define BN 128
#define BKo 16
#define NTILES 16

__global__ __launch_bounds__(256) void k_out(
    const float* __restrict__ x,
    const float* __restrict__ Wout,
    const float* __restrict__ bout,
    float* __restrict__ out)
{
    __shared__ __align__(16) float As[2][BM][20];    // 20.5 KB
    __shared__ __align__(16) float Bs[2][BKo][BN];   // 16 KB

    int t = threadIdx.x;
    int block_row = blockIdx.x * BM;
    int tx = t & 15, ty = t >> 4;     // 16x16 threads, 8x8 tile each

    // --- async tile loader (A: 128x16 floats, B: 16x128 floats) ---
    auto load_tile = [&](int kti, int buf) {
        const float* srcA = ((kti < 8) ? x : g_agg) + (kti & 7) * BKo;
#pragma unroll
        for (int cc = 0; cc < 2; cc++) {
            int c   = t + cc * 256;        // 0..511
            int row = c >> 2, q = c & 3;   // A: 4 x 16B chunks per row
            __pipeline_memcpy_async(&As[buf][row][q * 4],
                                    srcA + (size_t)(block_row + row) * 128 + q * 4, 16);
        }
#pragma unroll
        for (int cc = 0; cc < 2; cc++) {
            int c   = t + cc * 256;
            int row = c >> 5, col = c & 31;  // B: 32 x 16B chunks per row
            __pipeline_memcpy_async(&Bs[buf][row][col * 4],
                                    Wout + (size_t)(kti * BKo + row) * 128 + col * 4, 16);
        }
    };

    load_tile(0, 0);
    __pipeline_commit();
    __pipeline_wait_prior(0);
    __syncthreads();

    float acc[8][8];
#pragma unroll
    for (int i = 0; i < 8; i++)
#pragma unroll
        for (int j = 0; j < 8; j++) acc[i][j] = 0.f;

    for (int kti = 0; kti < NTILES; kti++) {
        int cur = kti & 1;
        if (kti < NTILES - 1) {
            load_tile(kti + 1, cur ^ 1);
            __pipeline_commit();
        }

#pragma unroll
        for (int kk = 0; kk < BKo; kk++) {
            float a[8], bb[8];
#pragma unroll
            for (int i = 0; i < 8; i++) a[i] = As[cur][ty * 8 + i][kk];
#pragma unroll
            for (int j = 0; j < 8; j++) bb[j] = Bs[cur][kk][tx * 8 + j];
#pragma unroll
            for (int i = 0; i < 8; i++)
#pragma unroll
                for (int j = 0; j < 8; j++)
                    acc[i][j] = fmaf(a[i], bb[j], acc[i][j]);
        }

        if (kti < NTILES - 1) __pipeline_wait_prior(0);
        __syncthreads();
    }

    float bias[8];
#pragma unroll
    for (int j = 0; j < 8; j++) bias[j] = bout[tx * 8 + j];

#pragma unroll
    for (int i = 0; i < 8; i++) {
        int row = block_row + ty * 8 + i;
        float v[8];
#pragma unroll
        for (int j = 0; j < 8; j++) v[j] = fmaxf(acc[i][j] + bias[j], 0.f);
        float4* dst = (float4*)(out + (size_t)row * 128 + tx * 8);
        dst[0] = make_float4(v[0], v[1], v[2], v[3]);
        dst[1] = make_float4(v[4], v[5], v[6], v[7]);
    }
}

// ============================================================
extern "C" void kernel_launch(void* const* d_in, const int* in_sizes, int n_in,
                              void* d_out, int out_size)
{
    const float* x    = (const float*)d_in[0];
    const float* Ws   = (const float*)d_in[1];
    const float* bs   = (const float*)d_in[2];
    const float* Wh   = (const float*)d_in[3];
    const float* bh   = (const float*)d_in[4];
    const float* Wout = (const float*)d_in[5];
    const float* bout = (const float*)d_in[6];
    // d_in[7] = batch (int64): contiguous equal-size graphs; layout implicit.
    float* out = (float*)d_out;

    k_embed<<<Ntot / 32, 256>>>(x, Ws, bs, Wh, bh);
    k_knn<<<dim3(Bg, 2), 512>>>();
    k_agg<<<Ntot / 8, 256>>>();
    k_out<<<Ntot / BM, 256>>>(x, Wout, bout, out);
}